// round 12
// baseline (speedup 1.0000x reference)
#include <cuda_runtime.h>
#include <math.h>

#define B 32
#define C 256
#define HW 56
#define BC (B*C)
#define POOL 7
#define NN 64
#define HEADS 8
#define HD 32
#define EPS 1e-5f

// ---------------- scratch ----------------
__device__ float g_mean_h[BC * HW];
__device__ float g_mean_w[BC * HW];
__device__ float g_attn_h[BC * HW];
__device__ float g_attn_w[BC * HW];
__device__ float g_pooled[BC * NN];
__device__ float g_bsum[B];
__device__ float g_bsumsq[B];
__device__ float g_ca[BC];

// ---------------- kernel 0: no-op (x3 -> ncu capture slot = k_means) -------
__global__ void k_tag() {}

// ---------------- kernel 1: row & col means of each 56x56 plane ------------
__global__ __launch_bounds__(256) void k_means(const float* __restrict__ x) {
    __shared__ float sp[HW][HW + 1];
    int bc = blockIdx.x, tid = threadIdx.x;
    if (tid == 0 && bc < B) { g_bsum[bc] = 0.f; g_bsumsq[bc] = 0.f; }
    const float4* xp = (const float4*)(x + (size_t)bc * HW * HW);
    #pragma unroll
    for (int k = 0; k < 4; ++k) {
        int f = tid + 256 * k;
        if (f < 784) {
            float4 v = xp[f];
            int r = f / 14, c = (f - r * 14) * 4;
            sp[r][c]     = v.x;
            sp[r][c + 1] = v.y;
            sp[r][c + 2] = v.z;
            sp[r][c + 3] = v.w;
        }
    }
    __syncthreads();
    if (tid < HW) {
        float rs = 0.f, cs = 0.f;
        #pragma unroll
        for (int w = 0; w < HW; ++w) { rs += sp[tid][w]; cs += sp[w][tid]; }
        g_mean_h[bc * HW + tid] = rs * (1.f / 56.f);
        g_mean_w[bc * HW + tid] = cs * (1.f / 56.f);
    }
}

// ---------------- kernel 2: sa_branch (dwconv -> GN(4) -> sigmoid) ---------
__global__ __launch_bounds__(512) void k_sa(
    const float* __restrict__ w3, const float* __restrict__ b3,
    const float* __restrict__ w5, const float* __restrict__ b5,
    const float* __restrict__ w7, const float* __restrict__ b7,
    const float* __restrict__ w9, const float* __restrict__ b9,
    const float* __restrict__ sh, const float* __restrict__ bh,
    const float* __restrict__ sw, const float* __restrict__ bw)
{
    __shared__ __align__(16) float sin_[64 * HW];   // 3584 floats
    __shared__ float r1[16], r2[16], sstat[2];

    int g  = blockIdx.x;
    int b  = blockIdx.y;
    int br = blockIdx.z;
    const float* in  = (br == 0) ? g_mean_h : g_mean_w;
    float*       out = (br == 0) ? g_attn_h : g_attn_w;
    const float* sc  = (br == 0) ? sh : sw;
    const float* bi  = (br == 0) ? bh : bw;
    const float* wf; const float* bf; int ksz;
    if (g == 0)      { wf = w3; bf = b3; ksz = 3; }
    else if (g == 1) { wf = w5; bf = b5; ksz = 5; }
    else if (g == 2) { wf = w7; bf = b7; ksz = 7; }
    else             { wf = w9; bf = b9; ksz = 9; }
    int pad = ksz >> 1;

    int tid = threadIdx.x;
    size_t base = ((size_t)b * C + g * 64) * HW;
    const float4* in4 = (const float4*)(in + base);
    float4*       out4 = (float4*)(out + base);
    #pragma unroll
    for (int k = 0; k < 2; ++k) {
        int f = tid + 512 * k;
        if (f < 896) ((float4*)sin_)[f] = in4[f];
    }
    __syncthreads();

    float o[8];
    float s = 0.f, ss = 0.f;
    int   cch[2];
    #pragma unroll
    for (int k = 0; k < 2; ++k) {
        int f = tid + 512 * k;
        if (f < 896) {
            int c  = f / 14;
            int l0 = (f - c * 14) * 4;
            cch[k] = c;
            const float* row = sin_ + c * HW;
            #pragma unroll
            for (int q = 0; q < 4; ++q) {
                int l = l0 + q;
                float acc = bf[c];
                for (int j = 0; j < ksz; ++j) {
                    int idx = l + j - pad;
                    if (idx >= 0 && idx < HW) acc = fmaf(wf[c * ksz + j], row[idx], acc);
                }
                o[k * 4 + q] = acc;
                s += acc; ss = fmaf(acc, acc, ss);
            }
        } else cch[k] = -1;
    }
    int lane = tid & 31, wid = tid >> 5;
    #pragma unroll
    for (int off = 16; off; off >>= 1) { s += __shfl_xor_sync(~0u, s, off); ss += __shfl_xor_sync(~0u, ss, off); }
    if (lane == 0) { r1[wid] = s; r2[wid] = ss; }
    __syncthreads();
    if (tid == 0) {
        float a = 0.f, bs2 = 0.f;
        #pragma unroll
        for (int w = 0; w < 16; ++w) { a += r1[w]; bs2 += r2[w]; }
        float mean = a * (1.f / 3584.f);
        float var  = bs2 * (1.f / 3584.f) - mean * mean;
        sstat[0] = mean;
        sstat[1] = rsqrtf(var + EPS);
    }
    __syncthreads();
    float mean = sstat[0], rstd = sstat[1];
    #pragma unroll
    for (int k = 0; k < 2; ++k) {
        if (cch[k] >= 0) {
            int f = tid + 512 * k;
            int cg = g * 64 + cch[k];
            float a_ = rstd * sc[cg], b_ = bi[cg] - mean * a_;
            float4 v;
            v.x = 1.f / (1.f + __expf(-(o[k*4+0] * a_ + b_)));
            v.y = 1.f / (1.f + __expf(-(o[k*4+1] * a_ + b_)));
            v.z = 1.f / (1.f + __expf(-(o[k*4+2] * a_ + b_)));
            v.w = 1.f / (1.f + __expf(-(o[k*4+3] * a_ + b_)));
            out4[f] = v;
        }
    }
}

// ---------------- kernel 3: pooled xg + per-batch stats (register bands) ---
__global__ __launch_bounds__(256) void k_pool(const float* __restrict__ x) {
    __shared__ __align__(16) float vs[2][8 * 60];   // [plane][band*60 + col]
    __shared__ __align__(16) float sah[2][HW];
    __shared__ __align__(16) float saw[2][HW];
    __shared__ float rs_[4], rss_[4];
    int pair = blockIdx.x, tid = threadIdx.x;
    int grp = tid >> 7;
    int t   = tid & 127;
    int bc  = pair * 2 + grp;
    int b   = bc >> 8;
    if (t < HW) {
        sah[grp][t] = g_attn_h[bc * HW + t];
        saw[grp][t] = g_attn_w[bc * HW + t];
    }
    __syncthreads();
    const float4* xp = (const float4*)(x + (size_t)bc * HW * HW);
    if (t < 112) {
        int i = t / 14, c4 = t - i * 14;
        float4 v[7];
        #pragma unroll
        for (int u = 0; u < 7; ++u) v[u] = xp[(7 * i + u) * 14 + c4];
        float4 acc = make_float4(0.f, 0.f, 0.f, 0.f);
        #pragma unroll
        for (int u = 0; u < 7; ++u) {
            float a = sah[grp][7 * i + u];
            acc.x = fmaf(v[u].x, a, acc.x);
            acc.y = fmaf(v[u].y, a, acc.y);
            acc.z = fmaf(v[u].z, a, acc.z);
            acc.w = fmaf(v[u].w, a, acc.w);
        }
        float4 w4 = ((const float4*)saw[grp])[c4];
        acc.x *= w4.x; acc.y *= w4.y; acc.z *= w4.z; acc.w *= w4.w;
        ((float4*)(vs[grp] + i * 60))[c4] = acc;
    }
    __syncthreads();
    float pv = 0.f;
    if (t < NN) {
        int i = t >> 3, j = t & 7;
        const float* p = vs[grp] + i * 60 + 7 * j;
        float sum = ((p[0] + p[1]) + (p[2] + p[3])) + ((p[4] + p[5]) + p[6]);
        pv = sum * (1.f / 49.f);
        g_pooled[bc * NN + t] = pv;
    }
    float s = pv, ss = pv * pv;
    #pragma unroll
    for (int o = 16; o; o >>= 1) { s += __shfl_xor_sync(~0u, s, o); ss += __shfl_xor_sync(~0u, ss, o); }
    int lane = tid & 31, wid = tid >> 5;
    if (lane == 0 && (wid == 0 || wid == 1)) { rs_[wid] = s; rss_[wid] = ss; }
    if (lane == 0 && (wid == 4 || wid == 5)) { rs_[wid - 2] = s; rss_[wid - 2] = ss; }
    __syncthreads();
    if (tid == 0) {
        atomicAdd(&g_bsum[b],   (rs_[0]  + rs_[1])  + (rs_[2]  + rs_[3]));
        atomicAdd(&g_bsumsq[b], (rss_[0] + rss_[1]) + (rss_[2] + rss_[3]));
    }
}

// ---------------- kernel 4: attention -> channel gate ----------------------
__global__ __launch_bounds__(256) void k_attn(
    const float* __restrict__ ns, const float* __restrict__ nb,
    const float* __restrict__ qw, const float* __restrict__ kw,
    const float* __restrict__ vw)
{
    __shared__ __align__(16) float xs[HD * 68];
    __shared__ float svbar[HD];
    int h = blockIdx.x, b = blockIdx.y;
    float bs = g_bsum[b], bss = g_bsumsq[b];
    float mu = bs * (1.f / 16384.f);
    float var = bss * (1.f / 16384.f) - mu * mu;
    float rstd = rsqrtf(var + EPS);
    const float4* p4 = (const float4*)(g_pooled + ((size_t)b * C + h * HD) * NN);
    int tid = threadIdx.x;
    #pragma unroll
    for (int k = 0; k < 2; ++k) {
        int f = tid + 256 * k;
        float4 v = p4[f];
        int e = f >> 4;
        int c = h * HD + e;
        float a_ = rstd * ns[c], b_ = nb[c] - mu * a_;
        v.x = v.x * a_ + b_;
        v.y = v.y * a_ + b_;
        v.z = v.z * a_ + b_;
        v.w = v.w * a_ + b_;
        ((float4*)xs)[e * 17 + (f & 15)] = v;
    }
    __syncthreads();

    int wi = tid >> 5, lane = tid & 31;
    {
        float sv[4];
        #pragma unroll
        for (int dd = 0; dd < 4; ++dd) {
            int row = wi * 4 + dd;
            sv[dd] = xs[row * 68 + lane] + xs[row * 68 + lane + 32];
        }
        #pragma unroll
        for (int o = 16; o; o >>= 1)
            #pragma unroll
            for (int dd = 0; dd < 4; ++dd)
                sv[dd] += __shfl_xor_sync(~0u, sv[dd], o);
        if (lane == 0) {
            #pragma unroll
            for (int dd = 0; dd < 4; ++dd) {
                int row = wi * 4 + dd;
                svbar[row] = sv[dd] * (1.f / 64.f) * vw[h * HD + row];
            }
        }
    }
    __syncthreads();

    float kwe = kw[h * HD + lane];
    float vb  = svbar[lane];
    const float scale = 0.17677669529663687f;  // 32^-0.5
    int d0 = wi * 4;
    const float4* xs4 = (const float4*)xs;

    float acc[4];
    #pragma unroll
    for (int dd = 0; dd < 4; ++dd) acc[dd] = 0.f;
    #pragma unroll
    for (int j = 0; j < 16; ++j) {
        float4 t = xs4[lane * 17 + j];
        #pragma unroll
        for (int dd = 0; dd < 4; ++dd) {
            float4 q = xs4[(d0 + dd) * 17 + j];
            acc[dd] = fmaf(t.x, q.x, acc[dd]);
            acc[dd] = fmaf(t.y, q.y, acc[dd]);
            acc[dd] = fmaf(t.z, q.z, acc[dd]);
            acc[dd] = fmaf(t.w, q.w, acc[dd]);
        }
    }
    float sarr[4];
    #pragma unroll
    for (int dd = 0; dd < 4; ++dd)
        sarr[dd] = acc[dd] * qw[h * HD + d0 + dd] * kwe * scale;

    float m[4], pe[4], Z[4], num[4];
    #pragma unroll
    for (int dd = 0; dd < 4; ++dd) m[dd] = sarr[dd];
    #pragma unroll
    for (int o = 16; o; o >>= 1)
        #pragma unroll
        for (int dd = 0; dd < 4; ++dd)
            m[dd] = fmaxf(m[dd], __shfl_xor_sync(~0u, m[dd], o));
    #pragma unroll
    for (int dd = 0; dd < 4; ++dd) {
        pe[dd]  = __expf(sarr[dd] - m[dd]);
        Z[dd]   = pe[dd];
        num[dd] = pe[dd] * vb;
    }
    #pragma unroll
    for (int o = 16; o; o >>= 1)
        #pragma unroll
        for (int dd = 0; dd < 4; ++dd) {
            Z[dd]   += __shfl_xor_sync(~0u, Z[dd], o);
            num[dd] += __shfl_xor_sync(~0u, num[dd], o);
        }
    if (lane == 0) {
        #pragma unroll
        for (int dd = 0; dd < 4; ++dd)
            g_ca[b * C + h * HD + d0 + dd] = 1.f / (1.f + __expf(-(num[dd] / Z[dd])));
    }
}

// ---------------- kernel 5: out = ca * x * ah * aw -------------------------
__global__ __launch_bounds__(256) void k_final(const float* __restrict__ x,
                                               float* __restrict__ out) {
    __shared__ float sca[HW], saw[HW];
    int bc = blockIdx.x, tid = threadIdx.x;
    float ca = g_ca[bc];
    if (tid < HW)                     sca[tid] = ca * g_attn_h[bc * HW + tid];
    else if (tid >= 64 && tid < 120)  saw[tid - 64] = g_attn_w[bc * HW + tid - 64];
    __syncthreads();
    const float4* xp = (const float4*)(x + (size_t)bc * HW * HW);
    float4*       op = (float4*)(out + (size_t)bc * HW * HW);
    float4 v[4]; int f[4]; bool valid[4];
    #pragma unroll
    for (int k = 0; k < 4; ++k) {
        f[k] = tid + 256 * k;
        valid[k] = (f[k] < 784);
        if (valid[k]) v[k] = xp[f[k]];
    }
    #pragma unroll
    for (int k = 0; k < 4; ++k) {
        if (valid[k]) {
            int hrow = f[k] / 14;
            int w4   = (f[k] - hrow * 14) * 4;
            float s = sca[hrow];
            float4 o = v[k];
            o.x *= s * saw[w4 + 0];
            o.y *= s * saw[w4 + 1];
            o.z *= s * saw[w4 + 2];
            o.w *= s * saw[w4 + 3];
            op[f[k]] = o;
        }
    }
}

// ---------------- launch ---------------------------------------------------
extern "C" void kernel_launch(void* const* d_in, const int* in_sizes, int n_in,
                              void* d_out, int out_size) {
    const float* x  = (const float*)d_in[0];
    const float* w3 = (const float*)d_in[1];
    const float* b3 = (const float*)d_in[2];
    const float* w5 = (const float*)d_in[3];
    const float* b5 = (const float*)d_in[4];
    const float* w7 = (const float*)d_in[5];
    const float* b7 = (const float*)d_in[6];
    const float* w9 = (const float*)d_in[7];
    const float* b9 = (const float*)d_in[8];
    const float* nhs = (const float*)d_in[9];
    const float* nhb = (const float*)d_in[10];
    const float* nws = (const float*)d_in[11];
    const float* nwb = (const float*)d_in[12];
    const float* ns  = (const float*)d_in[13];
    const float* nb  = (const float*)d_in[14];
    const float* qw  = (const float*)d_in[15];
    const float* kw  = (const float*)d_in[16];
    const float* vw  = (const float*)d_in[17];
    float* out = (float*)d_out;

    k_tag<<<1, 32>>>();   // slot 0
    k_tag<<<1, 32>>>();   // slot 1
    k_tag<<<1, 32>>>();   // slot 2 -> ncu capture slot 3 = k_means
    k_means<<<BC, 256>>>(x);
    k_sa<<<dim3(4, B, 2), 512>>>(w3, b3, w5, b5, w7, b7, w9, b9, nhs, nhb, nws, nwb);
    k_pool<<<BC / 2, 256>>>(x);
    k_attn<<<dim3(HEADS, B), 256>>>(ns, nb, qw, kw, vw);
    k_final<<<BC, 256>>>(x, out);
}

// round 13
// speedup vs baseline: 1.0232x; 1.0232x over previous
#include <cuda_runtime.h>
#include <math.h>

#define B 32
#define C 256
#define HW 56
#define BC (B*C)
#define POOL 7
#define NN 64
#define HEADS 8
#define HD 32
#define EPS 1e-5f

// ---------------- scratch ----------------
__device__ float g_mean_h[BC * HW];
__device__ float g_mean_w[BC * HW];
__device__ float g_attn_h[BC * HW];
__device__ float g_attn_w[BC * HW];
__device__ float g_pooled[BC * NN];
__device__ float g_bsum[B];
__device__ float g_bsumsq[B];
__device__ float g_ca[BC];

// ---------------- kernel 1: row & col means of each 56x56 plane ------------
__global__ __launch_bounds__(256) void k_means(const float* __restrict__ x) {
    __shared__ float sp[HW][HW + 1];
    int bc = blockIdx.x, tid = threadIdx.x;
    if (tid == 0 && bc < B) { g_bsum[bc] = 0.f; g_bsumsq[bc] = 0.f; }
    const float4* xp = (const float4*)(x + (size_t)bc * HW * HW);
    #pragma unroll
    for (int k = 0; k < 4; ++k) {
        int f = tid + 256 * k;
        if (f < 784) {
            float4 v = xp[f];
            int r = f / 14, c = (f - r * 14) * 4;
            sp[r][c]     = v.x;
            sp[r][c + 1] = v.y;
            sp[r][c + 2] = v.z;
            sp[r][c + 3] = v.w;
        }
    }
    __syncthreads();
    if (tid < HW) {
        float rs = 0.f, cs = 0.f;
        #pragma unroll
        for (int w = 0; w < HW; ++w) { rs += sp[tid][w]; cs += sp[w][tid]; }
        g_mean_h[bc * HW + tid] = rs * (1.f / 56.f);
        g_mean_w[bc * HW + tid] = cs * (1.f / 56.f);
    }
}

// ---------------- kernel 2: sa_branch (dwconv -> GN(4) -> sigmoid) ---------
__global__ __launch_bounds__(512) void k_sa(
    const float* __restrict__ w3, const float* __restrict__ b3,
    const float* __restrict__ w5, const float* __restrict__ b5,
    const float* __restrict__ w7, const float* __restrict__ b7,
    const float* __restrict__ w9, const float* __restrict__ b9,
    const float* __restrict__ sh, const float* __restrict__ bh,
    const float* __restrict__ sw, const float* __restrict__ bw)
{
    __shared__ __align__(16) float sin_[64 * HW];   // 3584 floats
    __shared__ float r1[16], r2[16], sstat[2];

    int g  = blockIdx.x;
    int b  = blockIdx.y;
    int br = blockIdx.z;
    const float* in  = (br == 0) ? g_mean_h : g_mean_w;
    float*       out = (br == 0) ? g_attn_h : g_attn_w;
    const float* sc  = (br == 0) ? sh : sw;
    const float* bi  = (br == 0) ? bh : bw;
    const float* wf; const float* bf; int ksz;
    if (g == 0)      { wf = w3; bf = b3; ksz = 3; }
    else if (g == 1) { wf = w5; bf = b5; ksz = 5; }
    else if (g == 2) { wf = w7; bf = b7; ksz = 7; }
    else             { wf = w9; bf = b9; ksz = 9; }
    int pad = ksz >> 1;

    int tid = threadIdx.x;
    size_t base = ((size_t)b * C + g * 64) * HW;
    const float4* in4 = (const float4*)(in + base);
    float4*       out4 = (float4*)(out + base);
    #pragma unroll
    for (int k = 0; k < 2; ++k) {
        int f = tid + 512 * k;
        if (f < 896) ((float4*)sin_)[f] = in4[f];
    }
    __syncthreads();

    float o[8];
    float s = 0.f, ss = 0.f;
    int   cch[2];
    #pragma unroll
    for (int k = 0; k < 2; ++k) {
        int f = tid + 512 * k;
        if (f < 896) {
            int c  = f / 14;
            int l0 = (f - c * 14) * 4;
            cch[k] = c;
            const float* row = sin_ + c * HW;
            #pragma unroll
            for (int q = 0; q < 4; ++q) {
                int l = l0 + q;
                float acc = bf[c];
                for (int j = 0; j < ksz; ++j) {
                    int idx = l + j - pad;
                    if (idx >= 0 && idx < HW) acc = fmaf(wf[c * ksz + j], row[idx], acc);
                }
                o[k * 4 + q] = acc;
                s += acc; ss = fmaf(acc, acc, ss);
            }
        } else cch[k] = -1;
    }
    int lane = tid & 31, wid = tid >> 5;
    #pragma unroll
    for (int off = 16; off; off >>= 1) { s += __shfl_xor_sync(~0u, s, off); ss += __shfl_xor_sync(~0u, ss, off); }
    if (lane == 0) { r1[wid] = s; r2[wid] = ss; }
    __syncthreads();
    if (tid == 0) {
        float a = 0.f, bs2 = 0.f;
        #pragma unroll
        for (int w = 0; w < 16; ++w) { a += r1[w]; bs2 += r2[w]; }
        float mean = a * (1.f / 3584.f);
        float var  = bs2 * (1.f / 3584.f) - mean * mean;
        sstat[0] = mean;
        sstat[1] = rsqrtf(var + EPS);
    }
    __syncthreads();
    float mean = sstat[0], rstd = sstat[1];
    #pragma unroll
    for (int k = 0; k < 2; ++k) {
        if (cch[k] >= 0) {
            int f = tid + 512 * k;
            int cg = g * 64 + cch[k];
            float a_ = rstd * sc[cg], b_ = bi[cg] - mean * a_;
            float4 v;
            v.x = 1.f / (1.f + __expf(-(o[k*4+0] * a_ + b_)));
            v.y = 1.f / (1.f + __expf(-(o[k*4+1] * a_ + b_)));
            v.z = 1.f / (1.f + __expf(-(o[k*4+2] * a_ + b_)));
            v.w = 1.f / (1.f + __expf(-(o[k*4+3] * a_ + b_)));
            out4[f] = v;
        }
    }
}

// ---------------- kernel 3: pooled xg + per-batch stats (register bands) ---
__global__ __launch_bounds__(256) void k_pool(const float* __restrict__ x) {
    __shared__ __align__(16) float vs[2][8 * 60];   // [plane][band*60 + col]
    __shared__ __align__(16) float sah[2][HW];
    __shared__ __align__(16) float saw[2][HW];
    __shared__ float rs_[4], rss_[4];
    int pair = blockIdx.x, tid = threadIdx.x;
    int grp = tid >> 7;
    int t   = tid & 127;
    int bc  = pair * 2 + grp;
    int b   = bc >> 8;
    if (t < HW) {
        sah[grp][t] = g_attn_h[bc * HW + t];
        saw[grp][t] = g_attn_w[bc * HW + t];
    }
    __syncthreads();
    const float4* xp = (const float4*)(x + (size_t)bc * HW * HW);
    if (t < 112) {
        int i = t / 14, c4 = t - i * 14;
        float4 v[7];
        #pragma unroll
        for (int u = 0; u < 7; ++u) v[u] = xp[(7 * i + u) * 14 + c4];
        float4 acc = make_float4(0.f, 0.f, 0.f, 0.f);
        #pragma unroll
        for (int u = 0; u < 7; ++u) {
            float a = sah[grp][7 * i + u];
            acc.x = fmaf(v[u].x, a, acc.x);
            acc.y = fmaf(v[u].y, a, acc.y);
            acc.z = fmaf(v[u].z, a, acc.z);
            acc.w = fmaf(v[u].w, a, acc.w);
        }
        float4 w4 = ((const float4*)saw[grp])[c4];
        acc.x *= w4.x; acc.y *= w4.y; acc.z *= w4.z; acc.w *= w4.w;
        ((float4*)(vs[grp] + i * 60))[c4] = acc;
    }
    __syncthreads();
    float pv = 0.f;
    if (t < NN) {
        int i = t >> 3, j = t & 7;
        const float* p = vs[grp] + i * 60 + 7 * j;
        float sum = ((p[0] + p[1]) + (p[2] + p[3])) + ((p[4] + p[5]) + p[6]);
        pv = sum * (1.f / 49.f);
        g_pooled[bc * NN + t] = pv;
    }
    float s = pv, ss = pv * pv;
    #pragma unroll
    for (int o = 16; o; o >>= 1) { s += __shfl_xor_sync(~0u, s, o); ss += __shfl_xor_sync(~0u, ss, o); }
    int lane = tid & 31, wid = tid >> 5;
    if (lane == 0 && (wid == 0 || wid == 1)) { rs_[wid] = s; rss_[wid] = ss; }
    if (lane == 0 && (wid == 4 || wid == 5)) { rs_[wid - 2] = s; rss_[wid - 2] = ss; }
    __syncthreads();
    if (tid == 0) {
        atomicAdd(&g_bsum[b],   (rs_[0]  + rs_[1])  + (rs_[2]  + rs_[3]));
        atomicAdd(&g_bsumsq[b], (rss_[0] + rss_[1]) + (rss_[2] + rss_[3]));
    }
}

// ---------------- kernel 4: attention -> channel gate ----------------------
// vbar fused into the Gram loop: lane e accumulates its own row sum while
// computing dot products -> no vbar phase, one fewer barrier.
__global__ __launch_bounds__(256) void k_attn(
    const float* __restrict__ ns, const float* __restrict__ nb,
    const float* __restrict__ qw, const float* __restrict__ kw,
    const float* __restrict__ vw)
{
    __shared__ __align__(16) float xs[HD * 68];
    int h = blockIdx.x, b = blockIdx.y;
    float bs = g_bsum[b], bss = g_bsumsq[b];
    float mu = bs * (1.f / 16384.f);
    float var = bss * (1.f / 16384.f) - mu * mu;
    float rstd = rsqrtf(var + EPS);
    const float4* p4 = (const float4*)(g_pooled + ((size_t)b * C + h * HD) * NN);
    int tid = threadIdx.x;
    #pragma unroll
    for (int k = 0; k < 2; ++k) {
        int f = tid + 256 * k;
        float4 v = p4[f];
        int e = f >> 4;
        int c = h * HD + e;
        float a_ = rstd * ns[c], b_ = nb[c] - mu * a_;
        v.x = v.x * a_ + b_;
        v.y = v.y * a_ + b_;
        v.z = v.z * a_ + b_;
        v.w = v.w * a_ + b_;
        ((float4*)xs)[e * 17 + (f & 15)] = v;
    }
    __syncthreads();

    int wi = tid >> 5, lane = tid & 31;
    float kwe = kw[h * HD + lane];
    const float scale = 0.17677669529663687f;  // 32^-0.5
    int d0 = wi * 4;
    const float4* xs4 = (const float4*)xs;

    float acc[4];
    float tsum = 0.f;
    #pragma unroll
    for (int dd = 0; dd < 4; ++dd) acc[dd] = 0.f;
    #pragma unroll
    for (int j = 0; j < 16; ++j) {
        float4 t = xs4[lane * 17 + j];          // conflict-free LDS.128
        tsum += (t.x + t.y) + (t.z + t.w);      // row-e sum (vbar) for free
        #pragma unroll
        for (int dd = 0; dd < 4; ++dd) {
            float4 q = xs4[(d0 + dd) * 17 + j]; // broadcast LDS.128
            acc[dd] = fmaf(t.x, q.x, acc[dd]);
            acc[dd] = fmaf(t.y, q.y, acc[dd]);
            acc[dd] = fmaf(t.z, q.z, acc[dd]);
            acc[dd] = fmaf(t.w, q.w, acc[dd]);
        }
    }
    float vb = tsum * (1.f / 64.f) * vw[h * HD + lane];
    float sarr[4];
    #pragma unroll
    for (int dd = 0; dd < 4; ++dd)
        sarr[dd] = acc[dd] * qw[h * HD + d0 + dd] * kwe * scale;

    float m[4], pe[4], Z[4], num[4];
    #pragma unroll
    for (int dd = 0; dd < 4; ++dd) m[dd] = sarr[dd];
    #pragma unroll
    for (int o = 16; o; o >>= 1)
        #pragma unroll
        for (int dd = 0; dd < 4; ++dd)
            m[dd] = fmaxf(m[dd], __shfl_xor_sync(~0u, m[dd], o));
    #pragma unroll
    for (int dd = 0; dd < 4; ++dd) {
        pe[dd]  = __expf(sarr[dd] - m[dd]);
        Z[dd]   = pe[dd];
        num[dd] = pe[dd] * vb;
    }
    #pragma unroll
    for (int o = 16; o; o >>= 1)
        #pragma unroll
        for (int dd = 0; dd < 4; ++dd) {
            Z[dd]   += __shfl_xor_sync(~0u, Z[dd], o);
            num[dd] += __shfl_xor_sync(~0u, num[dd], o);
        }
    if (lane == 0) {
        #pragma unroll
        for (int dd = 0; dd < 4; ++dd)
            g_ca[b * C + h * HD + d0 + dd] = 1.f / (1.f + __expf(-(num[dd] / Z[dd])));
    }
}

// ---------------- kernel 5: out = ca * x * ah * aw -------------------------
__global__ __launch_bounds__(256) void k_final(const float* __restrict__ x,
                                               float* __restrict__ out) {
    __shared__ float sca[HW], saw[HW];
    int bc = blockIdx.x, tid = threadIdx.x;
    float ca = g_ca[bc];
    if (tid < HW)                     sca[tid] = ca * g_attn_h[bc * HW + tid];
    else if (tid >= 64 && tid < 120)  saw[tid - 64] = g_attn_w[bc * HW + tid - 64];
    __syncthreads();
    const float4* xp = (const float4*)(x + (size_t)bc * HW * HW);
    float4*       op = (float4*)(out + (size_t)bc * HW * HW);
    float4 v[4]; int f[4]; bool valid[4];
    #pragma unroll
    for (int k = 0; k < 4; ++k) {
        f[k] = tid + 256 * k;
        valid[k] = (f[k] < 784);
        if (valid[k]) v[k] = xp[f[k]];
    }
    #pragma unroll
    for (int k = 0; k < 4; ++k) {
        if (valid[k]) {
            int hrow = f[k] / 14;
            int w4   = (f[k] - hrow * 14) * 4;
            float s = sca[hrow];
            float4 o = v[k];
            o.x *= s * saw[w4 + 0];
            o.y *= s * saw[w4 + 1];
            o.z *= s * saw[w4 + 2];
            o.w *= s * saw[w4 + 3];
            op[f[k]] = o;
        }
    }
}

// ---------------- launch ---------------------------------------------------
extern "C" void kernel_launch(void* const* d_in, const int* in_sizes, int n_in,
                              void* d_out, int out_size) {
    const float* x  = (const float*)d_in[0];
    const float* w3 = (const float*)d_in[1];
    const float* b3 = (const float*)d_in[2];
    const float* w5 = (const float*)d_in[3];
    const float* b5 = (const float*)d_in[4];
    const float* w7 = (const float*)d_in[5];
    const float* b7 = (const float*)d_in[6];
    const float* w9 = (const float*)d_in[7];
    const float* b9 = (const float*)d_in[8];
    const float* nhs = (const float*)d_in[9];
    const float* nhb = (const float*)d_in[10];
    const float* nws = (const float*)d_in[11];
    const float* nwb = (const float*)d_in[12];
    const float* ns  = (const float*)d_in[13];
    const float* nb  = (const float*)d_in[14];
    const float* qw  = (const float*)d_in[15];
    const float* kw  = (const float*)d_in[16];
    const float* vw  = (const float*)d_in[17];
    float* out = (float*)d_out;

    k_means<<<BC, 256>>>(x);
    k_sa<<<dim3(4, B, 2), 512>>>(w3, b3, w5, b5, w7, b7, w9, b9, nhs, nhb, nws, nwb);
    k_pool<<<BC / 2, 256>>>(x);
    k_attn<<<dim3(HEADS, B), 256>>>(ns, nb, qw, kw, vw);
    k_final<<<BC, 256>>>(x, out);
}

// round 14
// speedup vs baseline: 1.0263x; 1.0030x over previous
#include <cuda_runtime.h>
#include <math.h>

#define B 32
#define C 256
#define HW 56
#define BC (B*C)
#define POOL 7
#define NN 64
#define HEADS 8
#define HD 32
#define EPS 1e-5f

// ---------------- scratch ----------------
__device__ float g_mean_h[BC * HW];
__device__ float g_mean_w[BC * HW];
__device__ float g_attn_h[BC * HW];
__device__ float g_attn_w[BC * HW];
__device__ float g_pooled[BC * NN];
__device__ float g_bsum[B];
__device__ float g_bsumsq[B];
__device__ float g_ca[BC];

// ---------------- kernel 1: row & col means of each 56x56 plane ------------
__global__ __launch_bounds__(256) void k_means(const float* __restrict__ x) {
    __shared__ float sp[HW][HW + 1];
    int bc = blockIdx.x, tid = threadIdx.x;
    if (tid == 0 && bc < B) { g_bsum[bc] = 0.f; g_bsumsq[bc] = 0.f; }
    const float4* xp = (const float4*)(x + (size_t)bc * HW * HW);
    #pragma unroll
    for (int k = 0; k < 4; ++k) {
        int f = tid + 256 * k;
        if (f < 784) {
            float4 v = xp[f];
            int r = f / 14, c = (f - r * 14) * 4;
            sp[r][c]     = v.x;
            sp[r][c + 1] = v.y;
            sp[r][c + 2] = v.z;
            sp[r][c + 3] = v.w;
        }
    }
    __syncthreads();
    if (tid < HW) {
        float rs = 0.f, cs = 0.f;
        #pragma unroll
        for (int w = 0; w < HW; ++w) { rs += sp[tid][w]; cs += sp[w][tid]; }
        g_mean_h[bc * HW + tid] = rs * (1.f / 56.f);
        g_mean_w[bc * HW + tid] = cs * (1.f / 56.f);
    }
}

// ---------------- kernel 2: sa_branch (dwconv -> GN(4) -> sigmoid) ---------
__global__ __launch_bounds__(512) void k_sa(
    const float* __restrict__ w3, const float* __restrict__ b3,
    const float* __restrict__ w5, const float* __restrict__ b5,
    const float* __restrict__ w7, const float* __restrict__ b7,
    const float* __restrict__ w9, const float* __restrict__ b9,
    const float* __restrict__ sh, const float* __restrict__ bh,
    const float* __restrict__ sw, const float* __restrict__ bw)
{
    __shared__ __align__(16) float sin_[64 * HW];   // 3584 floats
    __shared__ float r1[16], r2[16], sstat[2];

    int g  = blockIdx.x;
    int b  = blockIdx.y;
    int br = blockIdx.z;
    const float* in  = (br == 0) ? g_mean_h : g_mean_w;
    float*       out = (br == 0) ? g_attn_h : g_attn_w;
    const float* sc  = (br == 0) ? sh : sw;
    const float* bi  = (br == 0) ? bh : bw;
    const float* wf; const float* bf; int ksz;
    if (g == 0)      { wf = w3; bf = b3; ksz = 3; }
    else if (g == 1) { wf = w5; bf = b5; ksz = 5; }
    else if (g == 2) { wf = w7; bf = b7; ksz = 7; }
    else             { wf = w9; bf = b9; ksz = 9; }
    int pad = ksz >> 1;

    int tid = threadIdx.x;
    size_t base = ((size_t)b * C + g * 64) * HW;
    const float4* in4 = (const float4*)(in + base);
    float4*       out4 = (float4*)(out + base);
    #pragma unroll
    for (int k = 0; k < 2; ++k) {
        int f = tid + 512 * k;
        if (f < 896) ((float4*)sin_)[f] = in4[f];
    }
    __syncthreads();

    float o[8];
    float s = 0.f, ss = 0.f;
    int   cch[2];
    #pragma unroll
    for (int k = 0; k < 2; ++k) {
        int f = tid + 512 * k;
        if (f < 896) {
            int c  = f / 14;
            int l0 = (f - c * 14) * 4;
            cch[k] = c;
            const float* row = sin_ + c * HW;
            #pragma unroll
            for (int q = 0; q < 4; ++q) {
                int l = l0 + q;
                float acc = bf[c];
                for (int j = 0; j < ksz; ++j) {
                    int idx = l + j - pad;
                    if (idx >= 0 && idx < HW) acc = fmaf(wf[c * ksz + j], row[idx], acc);
                }
                o[k * 4 + q] = acc;
                s += acc; ss = fmaf(acc, acc, ss);
            }
        } else cch[k] = -1;
    }
    int lane = tid & 31, wid = tid >> 5;
    #pragma unroll
    for (int off = 16; off; off >>= 1) { s += __shfl_xor_sync(~0u, s, off); ss += __shfl_xor_sync(~0u, ss, off); }
    if (lane == 0) { r1[wid] = s; r2[wid] = ss; }
    __syncthreads();
    if (tid == 0) {
        float a = 0.f, bs2 = 0.f;
        #pragma unroll
        for (int w = 0; w < 16; ++w) { a += r1[w]; bs2 += r2[w]; }
        float mean = a * (1.f / 3584.f);
        float var  = bs2 * (1.f / 3584.f) - mean * mean;
        sstat[0] = mean;
        sstat[1] = rsqrtf(var + EPS);
    }
    __syncthreads();
    float mean = sstat[0], rstd = sstat[1];
    #pragma unroll
    for (int k = 0; k < 2; ++k) {
        if (cch[k] >= 0) {
            int f = tid + 512 * k;
            int cg = g * 64 + cch[k];
            float a_ = rstd * sc[cg], b_ = bi[cg] - mean * a_;
            float4 v;
            v.x = 1.f / (1.f + __expf(-(o[k*4+0] * a_ + b_)));
            v.y = 1.f / (1.f + __expf(-(o[k*4+1] * a_ + b_)));
            v.z = 1.f / (1.f + __expf(-(o[k*4+2] * a_ + b_)));
            v.w = 1.f / (1.f + __expf(-(o[k*4+3] * a_ + b_)));
            out4[f] = v;
        }
    }
}

// ---------------- kernel 3: pooled xg + per-batch stats (register bands) ---
__global__ __launch_bounds__(256) void k_pool(const float* __restrict__ x) {
    __shared__ __align__(16) float vs[2][8 * 60];   // [plane][band*60 + col]
    __shared__ __align__(16) float sah[2][HW];
    __shared__ __align__(16) float saw[2][HW];
    __shared__ float rs_[4], rss_[4];
    int pair = blockIdx.x, tid = threadIdx.x;
    int grp = tid >> 7;
    int t   = tid & 127;
    int bc  = pair * 2 + grp;
    int b   = bc >> 8;
    if (t < HW) {
        sah[grp][t] = g_attn_h[bc * HW + t];
        saw[grp][t] = g_attn_w[bc * HW + t];
    }
    __syncthreads();
    const float4* xp = (const float4*)(x + (size_t)bc * HW * HW);
    if (t < 112) {
        int i = t / 14, c4 = t - i * 14;
        float4 v[7];
        #pragma unroll
        for (int u = 0; u < 7; ++u) v[u] = xp[(7 * i + u) * 14 + c4];
        float4 acc = make_float4(0.f, 0.f, 0.f, 0.f);
        #pragma unroll
        for (int u = 0; u < 7; ++u) {
            float a = sah[grp][7 * i + u];
            acc.x = fmaf(v[u].x, a, acc.x);
            acc.y = fmaf(v[u].y, a, acc.y);
            acc.z = fmaf(v[u].z, a, acc.z);
            acc.w = fmaf(v[u].w, a, acc.w);
        }
        float4 w4 = ((const float4*)saw[grp])[c4];
        acc.x *= w4.x; acc.y *= w4.y; acc.z *= w4.z; acc.w *= w4.w;
        ((float4*)(vs[grp] + i * 60))[c4] = acc;
    }
    __syncthreads();
    float pv = 0.f;
    if (t < NN) {
        int i = t >> 3, j = t & 7;
        const float* p = vs[grp] + i * 60 + 7 * j;
        float sum = ((p[0] + p[1]) + (p[2] + p[3])) + ((p[4] + p[5]) + p[6]);
        pv = sum * (1.f / 49.f);
        g_pooled[bc * NN + t] = pv;
    }
    float s = pv, ss = pv * pv;
    #pragma unroll
    for (int o = 16; o; o >>= 1) { s += __shfl_xor_sync(~0u, s, o); ss += __shfl_xor_sync(~0u, ss, o); }
    int lane = tid & 31, wid = tid >> 5;
    if (lane == 0 && (wid == 0 || wid == 1)) { rs_[wid] = s; rss_[wid] = ss; }
    if (lane == 0 && (wid == 4 || wid == 5)) { rs_[wid - 2] = s; rss_[wid - 2] = ss; }
    __syncthreads();
    if (tid == 0) {
        atomicAdd(&g_bsum[b],   (rs_[0]  + rs_[1])  + (rs_[2]  + rs_[3]));
        atomicAdd(&g_bsumsq[b], (rss_[0] + rss_[1]) + (rss_[2] + rss_[3]));
    }
}

// ---------------- kernel 4: attention -> channel gate (d-split x2) ---------
// grid (head=8, batch=32, zslice=2), block 128 = 4 warps x 4 d-rows.
// vbar fused into Gram loop (lane e's row sum falls out of t).
__global__ __launch_bounds__(128) void k_attn(
    const float* __restrict__ ns, const float* __restrict__ nb,
    const float* __restrict__ qw, const float* __restrict__ kw,
    const float* __restrict__ vw)
{
    __shared__ __align__(16) float xs[HD * 68];
    int h = blockIdx.x, b = blockIdx.y, z = blockIdx.z;
    float bs = g_bsum[b], bss = g_bsumsq[b];
    float mu = bs * (1.f / 16384.f);
    float var = bss * (1.f / 16384.f) - mu * mu;
    float rstd = rsqrtf(var + EPS);
    const float4* p4 = (const float4*)(g_pooled + ((size_t)b * C + h * HD) * NN);
    int tid = threadIdx.x;
    #pragma unroll
    for (int k = 0; k < 4; ++k) {
        int f = tid + 128 * k;            // 0..511
        float4 v = p4[f];
        int e = f >> 4;                    // 16 float4 per row
        int c = h * HD + e;
        float a_ = rstd * ns[c], b_ = nb[c] - mu * a_;
        v.x = v.x * a_ + b_;
        v.y = v.y * a_ + b_;
        v.z = v.z * a_ + b_;
        v.w = v.w * a_ + b_;
        ((float4*)xs)[e * 17 + (f & 15)] = v;
    }
    __syncthreads();

    int wi = tid >> 5, lane = tid & 31;
    float kwe = kw[h * HD + lane];
    const float scale = 0.17677669529663687f;  // 32^-0.5
    int d0 = z * 16 + wi * 4;
    const float4* xs4 = (const float4*)xs;

    float acc[4];
    float tsum = 0.f;
    #pragma unroll
    for (int dd = 0; dd < 4; ++dd) acc[dd] = 0.f;
    #pragma unroll
    for (int j = 0; j < 16; ++j) {
        float4 t = xs4[lane * 17 + j];          // conflict-free LDS.128
        tsum += (t.x + t.y) + (t.z + t.w);      // row-e sum (vbar) for free
        #pragma unroll
        for (int dd = 0; dd < 4; ++dd) {
            float4 q = xs4[(d0 + dd) * 17 + j]; // broadcast LDS.128
            acc[dd] = fmaf(t.x, q.x, acc[dd]);
            acc[dd] = fmaf(t.y, q.y, acc[dd]);
            acc[dd] = fmaf(t.z, q.z, acc[dd]);
            acc[dd] = fmaf(t.w, q.w, acc[dd]);
        }
    }
    float vb = tsum * (1.f / 64.f) * vw[h * HD + lane];
    float sarr[4];
    #pragma unroll
    for (int dd = 0; dd < 4; ++dd)
        sarr[dd] = acc[dd] * qw[h * HD + d0 + dd] * kwe * scale;

    float m[4], pe[4], Z[4], num[4];
    #pragma unroll
    for (int dd = 0; dd < 4; ++dd) m[dd] = sarr[dd];
    #pragma unroll
    for (int o = 16; o; o >>= 1)
        #pragma unroll
        for (int dd = 0; dd < 4; ++dd)
            m[dd] = fmaxf(m[dd], __shfl_xor_sync(~0u, m[dd], o));
    #pragma unroll
    for (int dd = 0; dd < 4; ++dd) {
        pe[dd]  = __expf(sarr[dd] - m[dd]);
        Z[dd]   = pe[dd];
        num[dd] = pe[dd] * vb;
    }
    #pragma unroll
    for (int o = 16; o; o >>= 1)
        #pragma unroll
        for (int dd = 0; dd < 4; ++dd) {
            Z[dd]   += __shfl_xor_sync(~0u, Z[dd], o);
            num[dd] += __shfl_xor_sync(~0u, num[dd], o);
        }
    if (lane == 0) {
        #pragma unroll
        for (int dd = 0; dd < 4; ++dd)
            g_ca[b * C + h * HD + d0 + dd] = 1.f / (1.f + __expf(-(num[dd] / Z[dd])));
    }
}

// ---------------- kernel 5: out = ca * x * ah * aw -------------------------
__global__ __launch_bounds__(256) void k_final(const float* __restrict__ x,
                                               float* __restrict__ out) {
    __shared__ float sca[HW], saw[HW];
    int bc = blockIdx.x, tid = threadIdx.x;
    float ca = g_ca[bc];
    if (tid < HW)                     sca[tid] = ca * g_attn_h[bc * HW + tid];
    else if (tid >= 64 && tid < 120)  saw[tid - 64] = g_attn_w[bc * HW + tid - 64];
    __syncthreads();
    const float4* xp = (const float4*)(x + (size_t)bc * HW * HW);
    float4*       op = (float4*)(out + (size_t)bc * HW * HW);
    float4 v[4]; int f[4]; bool valid[4];
    #pragma unroll
    for (int k = 0; k < 4; ++k) {
        f[k] = tid + 256 * k;
        valid[k] = (f[k] < 784);
        if (valid[k]) v[k] = xp[f[k]];
    }
    #pragma unroll
    for (int k = 0; k < 4; ++k) {
        if (valid[k]) {
            int hrow = f[k] / 14;
            int w4   = (f[k] - hrow * 14) * 4;
            float s = sca[hrow];
            float4 o = v[k];
            o.x *= s * saw[w4 + 0];
            o.y *= s * saw[w4 + 1];
            o.z *= s * saw[w4 + 2];
            o.w *= s * saw[w4 + 3];
            op[f[k]] = o;
        }
    }
}

// ---------------- launch ---------------------------------------------------
extern "C" void kernel_launch(void* const* d_in, const int* in_sizes, int n_in,
                              void* d_out, int out_size) {
    const float* x  = (const float*)d_in[0];
    const float* w3 = (const float*)d_in[1];
    const float* b3 = (const float*)d_in[2];
    const float* w5 = (const float*)d_in[3];
    const float* b5 = (const float*)d_in[4];
    const float* w7 = (const float*)d_in[5];
    const float* b7 = (const float*)d_in[6];
    const float* w9 = (const float*)d_in[7];
    const float* b9 = (const float*)d_in[8];
    const float* nhs = (const float*)d_in[9];
    const float* nhb = (const float*)d_in[10];
    const float* nws = (const float*)d_in[11];
    const float* nwb = (const float*)d_in[12];
    const float* ns  = (const float*)d_in[13];
    const float* nb  = (const float*)d_in[14];
    const float* qw  = (const float*)d_in[15];
    const float* kw  = (const float*)d_in[16];
    const float* vw  = (const float*)d_in[17];
    float* out = (float*)d_out;

    k_means<<<BC, 256>>>(x);
    k_sa<<<dim3(4, B, 2), 512>>>(w3, b3, w5, b5, w7, b7, w9, b9, nhs, nhb, nws, nwb);
    k_pool<<<BC / 2, 256>>>(x);
    k_attn<<<dim3(HEADS, B, 2), 128>>>(ns, nb, qw, kw, vw);
    k_final<<<BC, 256>>>(x, out);
}

// round 15
// speedup vs baseline: 1.0567x; 1.0297x over previous
#include <cuda_runtime.h>
#include <math.h>

#define B 32
#define C 256
#define HW 56
#define BC (B*C)
#define POOL 7
#define NN 64
#define HEADS 8
#define HD 32
#define EPS 1e-5f

// ---------------- scratch ----------------
__device__ float g_mean_h[BC * HW];
__device__ float g_mean_w[BC * HW];
__device__ float g_attn_h[BC * HW];
__device__ float g_attn_w[BC * HW];
__device__ float g_pooled[BC * NN];
__device__ float g_bsum[B];
__device__ float g_bsumsq[B];
__device__ float g_ca[BC];

// ---------------- kernel 1: row & col means of each 56x56 plane ------------
__global__ __launch_bounds__(256) void k_means(const float* __restrict__ x) {
    __shared__ float sp[HW][HW + 1];
    int bc = blockIdx.x, tid = threadIdx.x;
    if (tid == 0 && bc < B) { g_bsum[bc] = 0.f; g_bsumsq[bc] = 0.f; }
    const float4* xp = (const float4*)(x + (size_t)bc * HW * HW);
    #pragma unroll
    for (int k = 0; k < 4; ++k) {
        int f = tid + 256 * k;
        if (f < 784) {
            float4 v = xp[f];
            int r = f / 14, c = (f - r * 14) * 4;
            sp[r][c]     = v.x;
            sp[r][c + 1] = v.y;
            sp[r][c + 2] = v.z;
            sp[r][c + 3] = v.w;
        }
    }
    __syncthreads();
    if (tid < HW) {
        float rs = 0.f, cs = 0.f;
        #pragma unroll
        for (int w = 0; w < HW; ++w) { rs += sp[tid][w]; cs += sp[w][tid]; }
        g_mean_h[bc * HW + tid] = rs * (1.f / 56.f);
        g_mean_w[bc * HW + tid] = cs * (1.f / 56.f);
    }
}

// ---------------- kernel 2: sa_branch (dwconv -> GN(4) -> sigmoid) ---------
__global__ __launch_bounds__(512) void k_sa(
    const float* __restrict__ w3, const float* __restrict__ b3,
    const float* __restrict__ w5, const float* __restrict__ b5,
    const float* __restrict__ w7, const float* __restrict__ b7,
    const float* __restrict__ w9, const float* __restrict__ b9,
    const float* __restrict__ sh, const float* __restrict__ bh,
    const float* __restrict__ sw, const float* __restrict__ bw)
{
    __shared__ __align__(16) float sin_[64 * HW];   // 3584 floats
    __shared__ float r1[16], r2[16], sstat[2];

    int g  = blockIdx.x;
    int b  = blockIdx.y;
    int br = blockIdx.z;
    const float* in  = (br == 0) ? g_mean_h : g_mean_w;
    float*       out = (br == 0) ? g_attn_h : g_attn_w;
    const float* sc  = (br == 0) ? sh : sw;
    const float* bi  = (br == 0) ? bh : bw;
    const float* wf; const float* bf; int ksz;
    if (g == 0)      { wf = w3; bf = b3; ksz = 3; }
    else if (g == 1) { wf = w5; bf = b5; ksz = 5; }
    else if (g == 2) { wf = w7; bf = b7; ksz = 7; }
    else             { wf = w9; bf = b9; ksz = 9; }
    int pad = ksz >> 1;

    int tid = threadIdx.x;
    size_t base = ((size_t)b * C + g * 64) * HW;
    const float4* in4 = (const float4*)(in + base);
    float4*       out4 = (float4*)(out + base);
    #pragma unroll
    for (int k = 0; k < 2; ++k) {
        int f = tid + 512 * k;
        if (f < 896) ((float4*)sin_)[f] = in4[f];
    }
    __syncthreads();

    float o[8];
    float s = 0.f, ss = 0.f;
    int   cch[2];
    #pragma unroll
    for (int k = 0; k < 2; ++k) {
        int f = tid + 512 * k;
        if (f < 896) {
            int c  = f / 14;
            int l0 = (f - c * 14) * 4;
            cch[k] = c;
            const float* row = sin_ + c * HW;
            #pragma unroll
            for (int q = 0; q < 4; ++q) {
                int l = l0 + q;
                float acc = bf[c];
                for (int j = 0; j < ksz; ++j) {
                    int idx = l + j - pad;
                    if (idx >= 0 && idx < HW) acc = fmaf(wf[c * ksz + j], row[idx], acc);
                }
                o[k * 4 + q] = acc;
                s += acc; ss = fmaf(acc, acc, ss);
            }
        } else cch[k] = -1;
    }
    int lane = tid & 31, wid = tid >> 5;
    #pragma unroll
    for (int off = 16; off; off >>= 1) { s += __shfl_xor_sync(~0u, s, off); ss += __shfl_xor_sync(~0u, ss, off); }
    if (lane == 0) { r1[wid] = s; r2[wid] = ss; }
    __syncthreads();
    if (tid == 0) {
        float a = 0.f, bs2 = 0.f;
        #pragma unroll
        for (int w = 0; w < 16; ++w) { a += r1[w]; bs2 += r2[w]; }
        float mean = a * (1.f / 3584.f);
        float var  = bs2 * (1.f / 3584.f) - mean * mean;
        sstat[0] = mean;
        sstat[1] = rsqrtf(var + EPS);
    }
    __syncthreads();
    float mean = sstat[0], rstd = sstat[1];
    #pragma unroll
    for (int k = 0; k < 2; ++k) {
        if (cch[k] >= 0) {
            int f = tid + 512 * k;
            int cg = g * 64 + cch[k];
            float a_ = rstd * sc[cg], b_ = bi[cg] - mean * a_;
            float4 v;
            v.x = 1.f / (1.f + __expf(-(o[k*4+0] * a_ + b_)));
            v.y = 1.f / (1.f + __expf(-(o[k*4+1] * a_ + b_)));
            v.z = 1.f / (1.f + __expf(-(o[k*4+2] * a_ + b_)));
            v.w = 1.f / (1.f + __expf(-(o[k*4+3] * a_ + b_)));
            out4[f] = v;
        }
    }
}

// ---------------- kernel 3: pooled xg + per-batch stats (register bands) ---
__global__ __launch_bounds__(256) void k_pool(const float* __restrict__ x) {
    __shared__ __align__(16) float vs[2][8 * 60];   // [plane][band*60 + col]
    __shared__ __align__(16) float sah[2][HW];
    __shared__ __align__(16) float saw[2][HW];
    __shared__ float rs_[4], rss_[4];
    int pair = blockIdx.x, tid = threadIdx.x;
    int grp = tid >> 7;
    int t   = tid & 127;
    int bc  = pair * 2 + grp;
    int b   = bc >> 8;
    if (t < HW) {
        sah[grp][t] = g_attn_h[bc * HW + t];
        saw[grp][t] = g_attn_w[bc * HW + t];
    }
    __syncthreads();
    const float4* xp = (const float4*)(x + (size_t)bc * HW * HW);
    if (t < 112) {
        int i = t / 14, c4 = t - i * 14;
        float4 v[7];
        #pragma unroll
        for (int u = 0; u < 7; ++u) v[u] = xp[(7 * i + u) * 14 + c4];
        float4 acc = make_float4(0.f, 0.f, 0.f, 0.f);
        #pragma unroll
        for (int u = 0; u < 7; ++u) {
            float a = sah[grp][7 * i + u];
            acc.x = fmaf(v[u].x, a, acc.x);
            acc.y = fmaf(v[u].y, a, acc.y);
            acc.z = fmaf(v[u].z, a, acc.z);
            acc.w = fmaf(v[u].w, a, acc.w);
        }
        float4 w4 = ((const float4*)saw[grp])[c4];
        acc.x *= w4.x; acc.y *= w4.y; acc.z *= w4.z; acc.w *= w4.w;
        ((float4*)(vs[grp] + i * 60))[c4] = acc;
    }
    __syncthreads();
    float pv = 0.f;
    if (t < NN) {
        int i = t >> 3, j = t & 7;
        const float* p = vs[grp] + i * 60 + 7 * j;
        float sum = ((p[0] + p[1]) + (p[2] + p[3])) + ((p[4] + p[5]) + p[6]);
        pv = sum * (1.f / 49.f);
        g_pooled[bc * NN + t] = pv;
    }
    float s = pv, ss = pv * pv;
    #pragma unroll
    for (int o = 16; o; o >>= 1) { s += __shfl_xor_sync(~0u, s, o); ss += __shfl_xor_sync(~0u, ss, o); }
    int lane = tid & 31, wid = tid >> 5;
    if (lane == 0 && (wid == 0 || wid == 1)) { rs_[wid] = s; rss_[wid] = ss; }
    if (lane == 0 && (wid == 4 || wid == 5)) { rs_[wid - 2] = s; rss_[wid - 2] = ss; }
    __syncthreads();
    if (tid == 0) {
        atomicAdd(&g_bsum[b],   (rs_[0]  + rs_[1])  + (rs_[2]  + rs_[3]));
        atomicAdd(&g_bsumsq[b], (rss_[0] + rss_[1]) + (rss_[2] + rss_[3]));
    }
}

// ---------------- kernel 4: attention -> channel gate ----------------------
__global__ __launch_bounds__(256) void k_attn(
    const float* __restrict__ ns, const float* __restrict__ nb,
    const float* __restrict__ qw, const float* __restrict__ kw,
    const float* __restrict__ vw)
{
    __shared__ __align__(16) float xs[HD * 68];
    __shared__ float svbar[HD];
    int h = blockIdx.x, b = blockIdx.y;
    float bs = g_bsum[b], bss = g_bsumsq[b];
    float mu = bs * (1.f / 16384.f);
    float var = bss * (1.f / 16384.f) - mu * mu;
    float rstd = rsqrtf(var + EPS);
    const float4* p4 = (const float4*)(g_pooled + ((size_t)b * C + h * HD) * NN);
    int tid = threadIdx.x;
    #pragma unroll
    for (int k = 0; k < 2; ++k) {
        int f = tid + 256 * k;
        float4 v = p4[f];
        int e = f >> 4;
        int c = h * HD + e;
        float a_ = rstd * ns[c], b_ = nb[c] - mu * a_;
        v.x = v.x * a_ + b_;
        v.y = v.y * a_ + b_;
        v.z = v.z * a_ + b_;
        v.w = v.w * a_ + b_;
        ((float4*)xs)[e * 17 + (f & 15)] = v;
    }
    __syncthreads();

    int wi = tid >> 5, lane = tid & 31;
    {
        float sv[4];
        #pragma unroll
        for (int dd = 0; dd < 4; ++dd) {
            int row = wi * 4 + dd;
            sv[dd] = xs[row * 68 + lane] + xs[row * 68 + lane + 32];
        }
        #pragma unroll
        for (int o = 16; o; o >>= 1)
            #pragma unroll
            for (int dd = 0; dd < 4; ++dd)
                sv[dd] += __shfl_xor_sync(~0u, sv[dd], o);
        if (lane == 0) {
            #pragma unroll
            for (int dd = 0; dd < 4; ++dd) {
                int row = wi * 4 + dd;
                svbar[row] = sv[dd] * (1.f / 64.f) * vw[h * HD + row];
            }
        }
    }
    __syncthreads();

    float kwe = kw[h * HD + lane];
    float vb  = svbar[lane];
    const float scale = 0.17677669529663687f;  // 32^-0.5
    int d0 = wi * 4;
    const float4* xs4 = (const float4*)xs;

    float acc[4];
    #pragma unroll
    for (int dd = 0; dd < 4; ++dd) acc[dd] = 0.f;
    #pragma unroll
    for (int j = 0; j < 16; ++j) {
        float4 t = xs4[lane * 17 + j];
        #pragma unroll
        for (int dd = 0; dd < 4; ++dd) {
            float4 q = xs4[(d0 + dd) * 17 + j];
            acc[dd] = fmaf(t.x, q.x, acc[dd]);
            acc[dd] = fmaf(t.y, q.y, acc[dd]);
            acc[dd] = fmaf(t.z, q.z, acc[dd]);
            acc[dd] = fmaf(t.w, q.w, acc[dd]);
        }
    }
    float sarr[4];
    #pragma unroll
    for (int dd = 0; dd < 4; ++dd)
        sarr[dd] = acc[dd] * qw[h * HD + d0 + dd] * kwe * scale;

    float m[4], pe[4], Z[4], num[4];
    #pragma unroll
    for (int dd = 0; dd < 4; ++dd) m[dd] = sarr[dd];
    #pragma unroll
    for (int o = 16; o; o >>= 1)
        #pragma unroll
        for (int dd = 0; dd < 4; ++dd)
            m[dd] = fmaxf(m[dd], __shfl_xor_sync(~0u, m[dd], o));
    #pragma unroll
    for (int dd = 0; dd < 4; ++dd) {
        pe[dd]  = __expf(sarr[dd] - m[dd]);
        Z[dd]   = pe[dd];
        num[dd] = pe[dd] * vb;
    }
    #pragma unroll
    for (int o = 16; o; o >>= 1)
        #pragma unroll
        for (int dd = 0; dd < 4; ++dd) {
            Z[dd]   += __shfl_xor_sync(~0u, Z[dd], o);
            num[dd] += __shfl_xor_sync(~0u, num[dd], o);
        }
    if (lane == 0) {
        #pragma unroll
        for (int dd = 0; dd < 4; ++dd)
            g_ca[b * C + h * HD + d0 + dd] = 1.f / (1.f + __expf(-(num[dd] / Z[dd])));
    }
}

// ---------------- kernel 5: out = ca * x * ah * aw (streaming ld/st) -------
__global__ __launch_bounds__(256) void k_final(const float* __restrict__ x,
                                               float* __restrict__ out) {
    __shared__ float sca[HW], saw[HW];
    int bc = blockIdx.x, tid = threadIdx.x;
    float ca = g_ca[bc];
    if (tid < HW)                     sca[tid] = ca * g_attn_h[bc * HW + tid];
    else if (tid >= 64 && tid < 120)  saw[tid - 64] = g_attn_w[bc * HW + tid - 64];
    __syncthreads();
    const float4* xp = (const float4*)(x + (size_t)bc * HW * HW);
    float4*       op = (float4*)(out + (size_t)bc * HW * HW);
    float4 v[4]; int f[4]; bool valid[4];
    #pragma unroll
    for (int k = 0; k < 4; ++k) {
        f[k] = tid + 256 * k;
        valid[k] = (f[k] < 784);
        if (valid[k]) v[k] = __ldcs(&xp[f[k]]);   // last use of x: evict-first
    }
    #pragma unroll
    for (int k = 0; k < 4; ++k) {
        if (valid[k]) {
            int hrow = f[k] / 14;
            int w4   = (f[k] - hrow * 14) * 4;
            float s = sca[hrow];
            float4 o = v[k];
            o.x *= s * saw[w4 + 0];
            o.y *= s * saw[w4 + 1];
            o.z *= s * saw[w4 + 2];
            o.w *= s * saw[w4 + 3];
            __stcs(&op[f[k]], o);                 // never re-read: streaming store
        }
    }
}

// ---------------- launch ---------------------------------------------------
extern "C" void kernel_launch(void* const* d_in, const int* in_sizes, int n_in,
                              void* d_out, int out_size) {
    const float* x  = (const float*)d_in[0];
    const float* w3 = (const float*)d_in[1];
    const float* b3 = (const float*)d_in[2];
    const float* w5 = (const float*)d_in[3];
    const float* b5 = (const float*)d_in[4];
    const float* w7 = (const float*)d_in[5];
    const float* b7 = (const float*)d_in[6];
    const float* w9 = (const float*)d_in[7];
    const float* b9 = (const float*)d_in[8];
    const float* nhs = (const float*)d_in[9];
    const float* nhb = (const float*)d_in[10];
    const float* nws = (const float*)d_in[11];
    const float* nwb = (const float*)d_in[12];
    const float* ns  = (const float*)d_in[13];
    const float* nb  = (const float*)d_in[14];
    const float* qw  = (const float*)d_in[15];
    const float* kw  = (const float*)d_in[16];
    const float* vw  = (const float*)d_in[17];
    float* out = (float*)d_out;

    k_means<<<BC, 256>>>(x);
    k_sa<<<dim3(4, B, 2), 512>>>(w3, b3, w5, b5, w7, b7, w9, b9, nhs, nhb, nws, nwb);
    k_pool<<<BC / 2, 256>>>(x);
    k_attn<<<dim3(HEADS, B), 256>>>(ns, nb, qw, kw, vw);
    k_final<<<BC, 256>>>(x, out);
}

// round 16
// speedup vs baseline: 1.1163x; 1.0563x over previous
#include <cuda_runtime.h>
#include <math.h>

#define B 32
#define C 256
#define HW 56
#define BC (B*C)
#define POOL 7
#define NN 64
#define HEADS 8
#define HD 32
#define EPS 1e-5f

// ---------------- scratch ----------------
__device__ float g_mean_h[BC * HW];
__device__ float g_mean_w[BC * HW];
__device__ float g_attn_h[BC * HW];
__device__ float g_attn_w[BC * HW];
__device__ float g_pooled[BC * NN];
__device__ float g_bsum[B];
__device__ float g_bsumsq[B];
__device__ float g_ca[BC];

// ---------------- kernel 1: row & col means of each 56x56 plane ------------
__global__ __launch_bounds__(256) void k_means(const float* __restrict__ x) {
    __shared__ float sp[HW][HW + 1];
    int bc = blockIdx.x, tid = threadIdx.x;
    if (tid == 0 && bc < B) { g_bsum[bc] = 0.f; g_bsumsq[bc] = 0.f; }
    const float4* xp = (const float4*)(x + (size_t)bc * HW * HW);
    #pragma unroll
    for (int k = 0; k < 4; ++k) {
        int f = tid + 256 * k;
        if (f < 784) {
            float4 v = xp[f];
            int r = f / 14, c = (f - r * 14) * 4;
            sp[r][c]     = v.x;
            sp[r][c + 1] = v.y;
            sp[r][c + 2] = v.z;
            sp[r][c + 3] = v.w;
        }
    }
    __syncthreads();
    if (tid < HW) {
        float rs = 0.f, cs = 0.f;
        #pragma unroll
        for (int w = 0; w < HW; ++w) { rs += sp[tid][w]; cs += sp[w][tid]; }
        g_mean_h[bc * HW + tid] = rs * (1.f / 56.f);
        g_mean_w[bc * HW + tid] = cs * (1.f / 56.f);
    }
}

// ---------------- kernel 2: sa_branch (dwconv -> GN(4) -> sigmoid) ---------
__global__ __launch_bounds__(512) void k_sa(
    const float* __restrict__ w3, const float* __restrict__ b3,
    const float* __restrict__ w5, const float* __restrict__ b5,
    const float* __restrict__ w7, const float* __restrict__ b7,
    const float* __restrict__ w9, const float* __restrict__ b9,
    const float* __restrict__ sh, const float* __restrict__ bh,
    const float* __restrict__ sw, const float* __restrict__ bw)
{
    __shared__ __align__(16) float sin_[64 * HW];   // 3584 floats
    __shared__ float r1[16], r2[16], sstat[2];

    int g  = blockIdx.x;
    int b  = blockIdx.y;
    int br = blockIdx.z;
    const float* in  = (br == 0) ? g_mean_h : g_mean_w;
    float*       out = (br == 0) ? g_attn_h : g_attn_w;
    const float* sc  = (br == 0) ? sh : sw;
    const float* bi  = (br == 0) ? bh : bw;
    const float* wf; const float* bf; int ksz;
    if (g == 0)      { wf = w3; bf = b3; ksz = 3; }
    else if (g == 1) { wf = w5; bf = b5; ksz = 5; }
    else if (g == 2) { wf = w7; bf = b7; ksz = 7; }
    else             { wf = w9; bf = b9; ksz = 9; }
    int pad = ksz >> 1;

    int tid = threadIdx.x;
    size_t base = ((size_t)b * C + g * 64) * HW;
    const float4* in4 = (const float4*)(in + base);
    float4*       out4 = (float4*)(out + base);
    #pragma unroll
    for (int k = 0; k < 2; ++k) {
        int f = tid + 512 * k;
        if (f < 896) ((float4*)sin_)[f] = in4[f];
    }
    __syncthreads();

    float o[8];
    float s = 0.f, ss = 0.f;
    int   cch[2];
    #pragma unroll
    for (int k = 0; k < 2; ++k) {
        int f = tid + 512 * k;
        if (f < 896) {
            int c  = f / 14;
            int l0 = (f - c * 14) * 4;
            cch[k] = c;
            const float* row = sin_ + c * HW;
            #pragma unroll
            for (int q = 0; q < 4; ++q) {
                int l = l0 + q;
                float acc = bf[c];
                for (int j = 0; j < ksz; ++j) {
                    int idx = l + j - pad;
                    if (idx >= 0 && idx < HW) acc = fmaf(wf[c * ksz + j], row[idx], acc);
                }
                o[k * 4 + q] = acc;
                s += acc; ss = fmaf(acc, acc, ss);
            }
        } else cch[k] = -1;
    }
    int lane = tid & 31, wid = tid >> 5;
    #pragma unroll
    for (int off = 16; off; off >>= 1) { s += __shfl_xor_sync(~0u, s, off); ss += __shfl_xor_sync(~0u, ss, off); }
    if (lane == 0) { r1[wid] = s; r2[wid] = ss; }
    __syncthreads();
    if (tid == 0) {
        float a = 0.f, bs2 = 0.f;
        #pragma unroll
        for (int w = 0; w < 16; ++w) { a += r1[w]; bs2 += r2[w]; }
        float mean = a * (1.f / 3584.f);
        float var  = bs2 * (1.f / 3584.f) - mean * mean;
        sstat[0] = mean;
        sstat[1] = rsqrtf(var + EPS);
    }
    __syncthreads();
    float mean = sstat[0], rstd = sstat[1];
    #pragma unroll
    for (int k = 0; k < 2; ++k) {
        if (cch[k] >= 0) {
            int f = tid + 512 * k;
            int cg = g * 64 + cch[k];
            float a_ = rstd * sc[cg], b_ = bi[cg] - mean * a_;
            float4 v;
            v.x = 1.f / (1.f + __expf(-(o[k*4+0] * a_ + b_)));
            v.y = 1.f / (1.f + __expf(-(o[k*4+1] * a_ + b_)));
            v.z = 1.f / (1.f + __expf(-(o[k*4+2] * a_ + b_)));
            v.w = 1.f / (1.f + __expf(-(o[k*4+3] * a_ + b_)));
            out4[f] = v;
        }
    }
}

// ---------------- kernel 3: pooled xg + per-batch stats (register bands) ---
// Block order REVERSED vs k_means: reads the freshest L2 lines first (LIFO).
__global__ __launch_bounds__(256) void k_pool(const float* __restrict__ x) {
    __shared__ __align__(16) float vs[2][8 * 60];   // [plane][band*60 + col]
    __shared__ __align__(16) float sah[2][HW];
    __shared__ __align__(16) float saw[2][HW];
    __shared__ float rs_[4], rss_[4];
    int pair = gridDim.x - 1 - blockIdx.x;          // reversed mapping
    int tid = threadIdx.x;
    int grp = tid >> 7;
    int t   = tid & 127;
    int bc  = pair * 2 + grp;
    int b   = bc >> 8;
    if (t < HW) {
        sah[grp][t] = g_attn_h[bc * HW + t];
        saw[grp][t] = g_attn_w[bc * HW + t];
    }
    __syncthreads();
    const float4* xp = (const float4*)(x + (size_t)bc * HW * HW);
    if (t < 112) {
        int i = t / 14, c4 = t - i * 14;
        float4 v[7];
        #pragma unroll
        for (int u = 0; u < 7; ++u) v[u] = xp[(7 * i + u) * 14 + c4];
        float4 acc = make_float4(0.f, 0.f, 0.f, 0.f);
        #pragma unroll
        for (int u = 0; u < 7; ++u) {
            float a = sah[grp][7 * i + u];
            acc.x = fmaf(v[u].x, a, acc.x);
            acc.y = fmaf(v[u].y, a, acc.y);
            acc.z = fmaf(v[u].z, a, acc.z);
            acc.w = fmaf(v[u].w, a, acc.w);
        }
        float4 w4 = ((const float4*)saw[grp])[c4];
        acc.x *= w4.x; acc.y *= w4.y; acc.z *= w4.z; acc.w *= w4.w;
        ((float4*)(vs[grp] + i * 60))[c4] = acc;
    }
    __syncthreads();
    float pv = 0.f;
    if (t < NN) {
        int i = t >> 3, j = t & 7;
        const float* p = vs[grp] + i * 60 + 7 * j;
        float sum = ((p[0] + p[1]) + (p[2] + p[3])) + ((p[4] + p[5]) + p[6]);
        pv = sum * (1.f / 49.f);
        g_pooled[bc * NN + t] = pv;
    }
    float s = pv, ss = pv * pv;
    #pragma unroll
    for (int o = 16; o; o >>= 1) { s += __shfl_xor_sync(~0u, s, o); ss += __shfl_xor_sync(~0u, ss, o); }
    int lane = tid & 31, wid = tid >> 5;
    if (lane == 0 && (wid == 0 || wid == 1)) { rs_[wid] = s; rss_[wid] = ss; }
    if (lane == 0 && (wid == 4 || wid == 5)) { rs_[wid - 2] = s; rss_[wid - 2] = ss; }
    __syncthreads();
    if (tid == 0) {
        atomicAdd(&g_bsum[b],   (rs_[0]  + rs_[1])  + (rs_[2]  + rs_[3]));
        atomicAdd(&g_bsumsq[b], (rss_[0] + rss_[1]) + (rss_[2] + rss_[3]));
    }
}

// ---------------- kernel 4: attention -> channel gate ----------------------
__global__ __launch_bounds__(256) void k_attn(
    const float* __restrict__ ns, const float* __restrict__ nb,
    const float* __restrict__ qw, const float* __restrict__ kw,
    const float* __restrict__ vw)
{
    __shared__ __align__(16) float xs[HD * 68];
    __shared__ float svbar[HD];
    int h = blockIdx.x, b = blockIdx.y;
    float bs = g_bsum[b], bss = g_bsumsq[b];
    float mu = bs * (1.f / 16384.f);
    float var = bss * (1.f / 16384.f) - mu * mu;
    float rstd = rsqrtf(var + EPS);
    const float4* p4 = (const float4*)(g_pooled + ((size_t)b * C + h * HD) * NN);
    int tid = threadIdx.x;
    #pragma unroll
    for (int k = 0; k < 2; ++k) {
        int f = tid + 256 * k;
        float4 v = p4[f];
        int e = f >> 4;
        int c = h * HD + e;
        float a_ = rstd * ns[c], b_ = nb[c] - mu * a_;
        v.x = v.x * a_ + b_;
        v.y = v.y * a_ + b_;
        v.z = v.z * a_ + b_;
        v.w = v.w * a_ + b_;
        ((float4*)xs)[e * 17 + (f & 15)] = v;
    }
    __syncthreads();

    int wi = tid >> 5, lane = tid & 31;
    {
        float sv[4];
        #pragma unroll
        for (int dd = 0; dd < 4; ++dd) {
            int row = wi * 4 + dd;
            sv[dd] = xs[row * 68 + lane] + xs[row * 68 + lane + 32];
        }
        #pragma unroll
        for (int o = 16; o; o >>= 1)
            #pragma unroll
            for (int dd = 0; dd < 4; ++dd)
                sv[dd] += __shfl_xor_sync(~0u, sv[dd], o);
        if (lane == 0) {
            #pragma unroll
            for (int dd = 0; dd < 4; ++dd) {
                int row = wi * 4 + dd;
                svbar[row] = sv[dd] * (1.f / 64.f) * vw[h * HD + row];
            }
        }
    }
    __syncthreads();

    float kwe = kw[h * HD + lane];
    float vb  = svbar[lane];
    const float scale = 0.17677669529663687f;  // 32^-0.5
    int d0 = wi * 4;
    const float4* xs4 = (const float4*)xs;

    float acc[4];
    #pragma unroll
    for (int dd = 0; dd < 4; ++dd) acc[dd] = 0.f;
    #pragma unroll
    for (int j = 0; j < 16; ++j) {
        float4 t = xs4[lane * 17 + j];
        #pragma unroll
        for (int dd = 0; dd < 4; ++dd) {
            float4 q = xs4[(d0 + dd) * 17 + j];
            acc[dd] = fmaf(t.x, q.x, acc[dd]);
            acc[dd] = fmaf(t.y, q.y, acc[dd]);
            acc[dd] = fmaf(t.z, q.z, acc[dd]);
            acc[dd] = fmaf(t.w, q.w, acc[dd]);
        }
    }
    float sarr[4];
    #pragma unroll
    for (int dd = 0; dd < 4; ++dd)
        sarr[dd] = acc[dd] * qw[h * HD + d0 + dd] * kwe * scale;

    float m[4], pe[4], Z[4], num[4];
    #pragma unroll
    for (int dd = 0; dd < 4; ++dd) m[dd] = sarr[dd];
    #pragma unroll
    for (int o = 16; o; o >>= 1)
        #pragma unroll
        for (int dd = 0; dd < 4; ++dd)
            m[dd] = fmaxf(m[dd], __shfl_xor_sync(~0u, m[dd], o));
    #pragma unroll
    for (int dd = 0; dd < 4; ++dd) {
        pe[dd]  = __expf(sarr[dd] - m[dd]);
        Z[dd]   = pe[dd];
        num[dd] = pe[dd] * vb;
    }
    #pragma unroll
    for (int o = 16; o; o >>= 1)
        #pragma unroll
        for (int dd = 0; dd < 4; ++dd) {
            Z[dd]   += __shfl_xor_sync(~0u, Z[dd], o);
            num[dd] += __shfl_xor_sync(~0u, num[dd], o);
        }
    if (lane == 0) {
        #pragma unroll
        for (int dd = 0; dd < 4; ++dd)
            g_ca[b * C + h * HD + d0 + dd] = 1.f / (1.f + __expf(-(num[dd] / Z[dd])));
    }
}

// ---------------- kernel 5: out = ca * x * ah * aw (streaming ld/st) -------
__global__ __launch_bounds__(256) void k_final(const float* __restrict__ x,
                                               float* __restrict__ out) {
    __shared__ float sca[HW], saw[HW];
    int bc = blockIdx.x, tid = threadIdx.x;
    float ca = g_ca[bc];
    if (tid < HW)                     sca[tid] = ca * g_attn_h[bc * HW + tid];
    else if (tid >= 64 && tid < 120)  saw[tid - 64] = g_attn_w[bc * HW + tid - 64];
    __syncthreads();
    const float4* xp = (const float4*)(x + (size_t)bc * HW * HW);
    float4*       op = (float4*)(out + (size_t)bc * HW * HW);
    float4 v[4]; int f[4]; bool valid[4];
    #pragma unroll
    for (int k = 0; k < 4; ++k) {
        f[k] = tid + 256 * k;
        valid[k] = (f[k] < 784);
        if (valid[k]) v[k] = __ldcs(&xp[f[k]]);   // last use of x: evict-first
    }
    #pragma unroll
    for (int k = 0; k < 4; ++k) {
        if (valid[k]) {
            int hrow = f[k] / 14;
            int w4   = (f[k] - hrow * 14) * 4;
            float s = sca[hrow];
            float4 o = v[k];
            o.x *= s * saw[w4 + 0];
            o.y *= s * saw[w4 + 1];
            o.z *= s * saw[w4 + 2];
            o.w *= s * saw[w4 + 3];
            __stcs(&op[f[k]], o);                 // never re-read: streaming store
        }
    }
}

// ---------------- launch ---------------------------------------------------
extern "C" void kernel_launch(void* const* d_in, const int* in_sizes, int n_in,
                              void* d_out, int out_size) {
    const float* x  = (const float*)d_in[0];
    const float* w3 = (const float*)d_in[1];
    const float* b3 = (const float*)d_in[2];
    const float* w5 = (const float*)d_in[3];
    const float* b5 = (const float*)d_in[4];
    const float* w7 = (const float*)d_in[5];
    const float* b7 = (const float*)d_in[6];
    const float* w9 = (const float*)d_in[7];
    const float* b9 = (const float*)d_in[8];
    const float* nhs = (const float*)d_in[9];
    const float* nhb = (const float*)d_in[10];
    const float* nws = (const float*)d_in[11];
    const float* nwb = (const float*)d_in[12];
    const float* ns  = (const float*)d_in[13];
    const float* nb  = (const float*)d_in[14];
    const float* qw  = (const float*)d_in[15];
    const float* kw  = (const float*)d_in[16];
    const float* vw  = (const float*)d_in[17];
    float* out = (float*)d_out;

    k_means<<<BC, 256>>>(x);
    k_sa<<<dim3(4, B, 2), 512>>>(w3, b3, w5, b5, w7, b7, w9, b9, nhs, nhb, nws, nwb);
    k_pool<<<BC / 2, 256>>>(x);
    k_attn<<<dim3(HEADS, B), 256>>>(ns, nb, qw, kw, vw);
    k_final<<<BC, 256>>>(x, out);
}

// round 17
// speedup vs baseline: 1.1793x; 1.0565x over previous
#include <cuda_runtime.h>
#include <math.h>

#define B 32
#define C 256
#define HW 56
#define BC (B*C)
#define POOL 7
#define NN 64
#define HEADS 8
#define HD 32
#define EPS 1e-5f

// ---------------- scratch ----------------
__device__ float g_mean_h[BC * HW];
__device__ float g_mean_w[BC * HW];
__device__ float g_attn_h[BC * HW];
__device__ float g_attn_w[BC * HW];
__device__ float g_pooled[BC * NN];
__device__ float g_bsum[B];
__device__ float g_bsumsq[B];
__device__ float g_ca[BC];

// ---------------- kernel 1: row & col means of each 56x56 plane ------------
__global__ __launch_bounds__(256) void k_means(const float* __restrict__ x) {
    __shared__ float sp[HW][HW + 1];
    int bc = blockIdx.x, tid = threadIdx.x;
    if (tid == 0 && bc < B) { g_bsum[bc] = 0.f; g_bsumsq[bc] = 0.f; }
    const float4* xp = (const float4*)(x + (size_t)bc * HW * HW);
    #pragma unroll
    for (int k = 0; k < 4; ++k) {
        int f = tid + 256 * k;
        if (f < 784) {
            float4 v = xp[f];
            int r = f / 14, c = (f - r * 14) * 4;
            sp[r][c]     = v.x;
            sp[r][c + 1] = v.y;
            sp[r][c + 2] = v.z;
            sp[r][c + 3] = v.w;
        }
    }
    __syncthreads();
    if (tid < HW) {
        float rs = 0.f, cs = 0.f;
        #pragma unroll
        for (int w = 0; w < HW; ++w) { rs += sp[tid][w]; cs += sp[w][tid]; }
        g_mean_h[bc * HW + tid] = rs * (1.f / 56.f);
        g_mean_w[bc * HW + tid] = cs * (1.f / 56.f);
    }
}

// ---------------- kernel 2: sa_branch (dwconv -> GN(4) -> sigmoid) ---------
// Triggers PDL completion at entry: successor (k_pool) may launch and run its
// x-load prologue concurrently.
__global__ __launch_bounds__(512) void k_sa(
    const float* __restrict__ w3, const float* __restrict__ b3,
    const float* __restrict__ w5, const float* __restrict__ b5,
    const float* __restrict__ w7, const float* __restrict__ b7,
    const float* __restrict__ w9, const float* __restrict__ b9,
    const float* __restrict__ sh, const float* __restrict__ bh,
    const float* __restrict__ sw, const float* __restrict__ bw)
{
    cudaTriggerProgrammaticLaunchCompletion();
    __shared__ __align__(16) float sin_[64 * HW];   // 3584 floats
    __shared__ float r1[16], r2[16], sstat[2];

    int g  = blockIdx.x;
    int b  = blockIdx.y;
    int br = blockIdx.z;
    const float* in  = (br == 0) ? g_mean_h : g_mean_w;
    float*       out = (br == 0) ? g_attn_h : g_attn_w;
    const float* sc  = (br == 0) ? sh : sw;
    const float* bi  = (br == 0) ? bh : bw;
    const float* wf; const float* bf; int ksz;
    if (g == 0)      { wf = w3; bf = b3; ksz = 3; }
    else if (g == 1) { wf = w5; bf = b5; ksz = 5; }
    else if (g == 2) { wf = w7; bf = b7; ksz = 7; }
    else             { wf = w9; bf = b9; ksz = 9; }
    int pad = ksz >> 1;

    int tid = threadIdx.x;
    size_t base = ((size_t)b * C + g * 64) * HW;
    const float4* in4 = (const float4*)(in + base);
    float4*       out4 = (float4*)(out + base);
    #pragma unroll
    for (int k = 0; k < 2; ++k) {
        int f = tid + 512 * k;
        if (f < 896) ((float4*)sin_)[f] = in4[f];
    }
    __syncthreads();

    float o[8];
    float s = 0.f, ss = 0.f;
    int   cch[2];
    #pragma unroll
    for (int k = 0; k < 2; ++k) {
        int f = tid + 512 * k;
        if (f < 896) {
            int c  = f / 14;
            int l0 = (f - c * 14) * 4;
            cch[k] = c;
            const float* row = sin_ + c * HW;
            #pragma unroll
            for (int q = 0; q < 4; ++q) {
                int l = l0 + q;
                float acc = bf[c];
                for (int j = 0; j < ksz; ++j) {
                    int idx = l + j - pad;
                    if (idx >= 0 && idx < HW) acc = fmaf(wf[c * ksz + j], row[idx], acc);
                }
                o[k * 4 + q] = acc;
                s += acc; ss = fmaf(acc, acc, ss);
            }
        } else cch[k] = -1;
    }
    int lane = tid & 31, wid = tid >> 5;
    #pragma unroll
    for (int off = 16; off; off >>= 1) { s += __shfl_xor_sync(~0u, s, off); ss += __shfl_xor_sync(~0u, ss, off); }
    if (lane == 0) { r1[wid] = s; r2[wid] = ss; }
    __syncthreads();
    if (tid == 0) {
        float a = 0.f, bs2 = 0.f;
        #pragma unroll
        for (int w = 0; w < 16; ++w) { a += r1[w]; bs2 += r2[w]; }
        float mean = a * (1.f / 3584.f);
        float var  = bs2 * (1.f / 3584.f) - mean * mean;
        sstat[0] = mean;
        sstat[1] = rsqrtf(var + EPS);
    }
    __syncthreads();
    float mean = sstat[0], rstd = sstat[1];
    #pragma unroll
    for (int k = 0; k < 2; ++k) {
        if (cch[k] >= 0) {
            int f = tid + 512 * k;
            int cg = g * 64 + cch[k];
            float a_ = rstd * sc[cg], b_ = bi[cg] - mean * a_;
            float4 v;
            v.x = 1.f / (1.f + __expf(-(o[k*4+0] * a_ + b_)));
            v.y = 1.f / (1.f + __expf(-(o[k*4+1] * a_ + b_)));
            v.z = 1.f / (1.f + __expf(-(o[k*4+2] * a_ + b_)));
            v.w = 1.f / (1.f + __expf(-(o[k*4+3] * a_ + b_)));
            out4[f] = v;
        }
    }
}

// ---------------- kernel 3: pooled xg + per-batch stats (register bands) ---
// PDL secondary of k_sa: x loads (independent) pre-sync; g_attn reads after
// cudaGridDependencySynchronize. Reversed block order (L2 LIFO reuse).
__global__ __launch_bounds__(256) void k_pool(const float* __restrict__ x) {
    __shared__ __align__(16) float vs[2][8 * 60];
    __shared__ __align__(16) float sah[2][HW];
    __shared__ __align__(16) float saw[2][HW];
    __shared__ float rs_[4], rss_[4];
    int pair = gridDim.x - 1 - blockIdx.x;          // reversed mapping
    int tid = threadIdx.x;
    int grp = tid >> 7;
    int t   = tid & 127;
    int bc  = pair * 2 + grp;
    int b   = bc >> 8;
    const float4* xp = (const float4*)(x + (size_t)bc * HW * HW);
    float4 v[7];
    int i = 0, c4 = 0;
    if (t < 112) {
        i = t / 14; c4 = t - i * 14;
        #pragma unroll
        for (int u = 0; u < 7; ++u) v[u] = xp[(7 * i + u) * 14 + c4];  // pre-sync
    }
    cudaGridDependencySynchronize();                // k_sa's g_attn now visible
    if (t < HW) {
        sah[grp][t] = g_attn_h[bc * HW + t];
        saw[grp][t] = g_attn_w[bc * HW + t];
    }
    __syncthreads();
    if (t < 112) {
        float4 acc = make_float4(0.f, 0.f, 0.f, 0.f);
        #pragma unroll
        for (int u = 0; u < 7; ++u) {
            float a = sah[grp][7 * i + u];
            acc.x = fmaf(v[u].x, a, acc.x);
            acc.y = fmaf(v[u].y, a, acc.y);
            acc.z = fmaf(v[u].z, a, acc.z);
            acc.w = fmaf(v[u].w, a, acc.w);
        }
        float4 w4 = ((const float4*)saw[grp])[c4];
        acc.x *= w4.x; acc.y *= w4.y; acc.z *= w4.z; acc.w *= w4.w;
        ((float4*)(vs[grp] + i * 60))[c4] = acc;
    }
    __syncthreads();
    float pv = 0.f;
    if (t < NN) {
        int pi = t >> 3, pj = t & 7;
        const float* p = vs[grp] + pi * 60 + 7 * pj;
        float sum = ((p[0] + p[1]) + (p[2] + p[3])) + ((p[4] + p[5]) + p[6]);
        pv = sum * (1.f / 49.f);
        g_pooled[bc * NN + t] = pv;
    }
    float s = pv, ss = pv * pv;
    #pragma unroll
    for (int o = 16; o; o >>= 1) { s += __shfl_xor_sync(~0u, s, o); ss += __shfl_xor_sync(~0u, ss, o); }
    int lane = tid & 31, wid = tid >> 5;
    if (lane == 0 && (wid == 0 || wid == 1)) { rs_[wid] = s; rss_[wid] = ss; }
    if (lane == 0 && (wid == 4 || wid == 5)) { rs_[wid - 2] = s; rss_[wid - 2] = ss; }
    __syncthreads();
    if (tid == 0) {
        atomicAdd(&g_bsum[b],   (rs_[0]  + rs_[1])  + (rs_[2]  + rs_[3]));
        atomicAdd(&g_bsumsq[b], (rss_[0] + rss_[1]) + (rss_[2] + rss_[3]));
    }
}

// ---------------- kernel 4: attention -> channel gate ----------------------
// Triggers PDL completion at entry: k_final may launch and run its x prologue.
__global__ __launch_bounds__(256) void k_attn(
    const float* __restrict__ ns, const float* __restrict__ nb,
    const float* __restrict__ qw, const float* __restrict__ kw,
    const float* __restrict__ vw)
{
    cudaTriggerProgrammaticLaunchCompletion();
    __shared__ __align__(16) float xs[HD * 68];
    __shared__ float svbar[HD];
    int h = blockIdx.x, b = blockIdx.y;
    float bs = g_bsum[b], bss = g_bsumsq[b];
    float mu = bs * (1.f / 16384.f);
    float var = bss * (1.f / 16384.f) - mu * mu;
    float rstd = rsqrtf(var + EPS);
    const float4* p4 = (const float4*)(g_pooled + ((size_t)b * C + h * HD) * NN);
    int tid = threadIdx.x;
    #pragma unroll
    for (int k = 0; k < 2; ++k) {
        int f = tid + 256 * k;
        float4 v = p4[f];
        int e = f >> 4;
        int c = h * HD + e;
        float a_ = rstd * ns[c], b_ = nb[c] - mu * a_;
        v.x = v.x * a_ + b_;
        v.y = v.y * a_ + b_;
        v.z = v.z * a_ + b_;
        v.w = v.w * a_ + b_;
        ((float4*)xs)[e * 17 + (f & 15)] = v;
    }
    __syncthreads();

    int wi = tid >> 5, lane = tid & 31;
    {
        float sv[4];
        #pragma unroll
        for (int dd = 0; dd < 4; ++dd) {
            int row = wi * 4 + dd;
            sv[dd] = xs[row * 68 + lane] + xs[row * 68 + lane + 32];
        }
        #pragma unroll
        for (int o = 16; o; o >>= 1)
            #pragma unroll
            for (int dd = 0; dd < 4; ++dd)
                sv[dd] += __shfl_xor_sync(~0u, sv[dd], o);
        if (lane == 0) {
            #pragma unroll
            for (int dd = 0; dd < 4; ++dd) {
                int row = wi * 4 + dd;
                svbar[row] = sv[dd] * (1.f / 64.f) * vw[h * HD + row];
            }
        }
    }
    __syncthreads();

    float kwe = kw[h * HD + lane];
    float vb  = svbar[lane];
    const float scale = 0.17677669529663687f;  // 32^-0.5
    int d0 = wi * 4;
    const float4* xs4 = (const float4*)xs;

    float acc[4];
    #pragma unroll
    for (int dd = 0; dd < 4; ++dd) acc[dd] = 0.f;
    #pragma unroll
    for (int j = 0; j < 16; ++j) {
        float4 t = xs4[lane * 17 + j];
        #pragma unroll
        for (int dd = 0; dd < 4; ++dd) {
            float4 q = xs4[(d0 + dd) * 17 + j];
            acc[dd] = fmaf(t.x, q.x, acc[dd]);
            acc[dd] = fmaf(t.y, q.y, acc[dd]);
            acc[dd] = fmaf(t.z, q.z, acc[dd]);
            acc[dd] = fmaf(t.w, q.w, acc[dd]);
        }
    }
    float sarr[4];
    #pragma unroll
    for (int dd = 0; dd < 4; ++dd)
        sarr[dd] = acc[dd] * qw[h * HD + d0 + dd] * kwe * scale;

    float m[4], pe[4], Z[4], num[4];
    #pragma unroll
    for (int dd = 0; dd < 4; ++dd) m[dd] = sarr[dd];
    #pragma unroll
    for (int o = 16; o; o >>= 1)
        #pragma unroll
        for (int dd = 0; dd < 4; ++dd)
            m[dd] = fmaxf(m[dd], __shfl_xor_sync(~0u, m[dd], o));
    #pragma unroll
    for (int dd = 0; dd < 4; ++dd) {
        pe[dd]  = __expf(sarr[dd] - m[dd]);
        Z[dd]   = pe[dd];
        num[dd] = pe[dd] * vb;
    }
    #pragma unroll
    for (int o = 16; o; o >>= 1)
        #pragma unroll
        for (int dd = 0; dd < 4; ++dd) {
            Z[dd]   += __shfl_xor_sync(~0u, Z[dd], o);
            num[dd] += __shfl_xor_sync(~0u, num[dd], o);
        }
    if (lane == 0) {
        #pragma unroll
        for (int dd = 0; dd < 4; ++dd)
            g_ca[b * C + h * HD + d0 + dd] = 1.f / (1.f + __expf(-(num[dd] / Z[dd])));
    }
}

// ---------------- kernel 5: out = ca * x * ah * aw (PDL secondary) ---------
// Pre-sync: stream x (.cs) + stage attn vectors (written by k_sa, complete).
// Post-sync: read g_ca (written by k_attn).
__global__ __launch_bounds__(256) void k_final(const float* __restrict__ x,
                                               float* __restrict__ out) {
    __shared__ float sah[HW], saw[HW];
    int bc = blockIdx.x, tid = threadIdx.x;
    const float4* xp = (const float4*)(x + (size_t)bc * HW * HW);
    float4*       op = (float4*)(out + (size_t)bc * HW * HW);
    float4 v[4]; int f[4]; bool valid[4];
    #pragma unroll
    for (int k = 0; k < 4; ++k) {
        f[k] = tid + 256 * k;
        valid[k] = (f[k] < 784);
        if (valid[k]) v[k] = __ldcs(&xp[f[k]]);   // last use of x: evict-first
    }
    if (tid < HW)                     sah[tid] = g_attn_h[bc * HW + tid];
    else if (tid >= 64 && tid < 120)  saw[tid - 64] = g_attn_w[bc * HW + tid - 64];
    __syncthreads();
    cudaGridDependencySynchronize();              // k_attn's g_ca now visible
    float ca = g_ca[bc];
    #pragma unroll
    for (int k = 0; k < 4; ++k) {
        if (valid[k]) {
            int hrow = f[k] / 14;
            int w4   = (f[k] - hrow * 14) * 4;
            float s = ca * sah[hrow];
            float4 o = v[k];
            o.x *= s * saw[w4 + 0];
            o.y *= s * saw[w4 + 1];
            o.z *= s * saw[w4 + 2];
            o.w *= s * saw[w4 + 3];
            __stcs(&op[f[k]], o);                 // never re-read: streaming store
        }
    }
}

// ---------------- launch ---------------------------------------------------
static void launch_pdl(void* fn, dim3 grid, dim3 block, void** args) {
    cudaLaunchConfig_t cfg = {};
    cfg.gridDim = grid;
    cfg.blockDim = block;
    cfg.stream = 0;
    cudaLaunchAttribute a[1];
    a[0].id = cudaLaunchAttributeProgrammaticStreamSerialization;
    a[0].val.programmaticStreamSerializationAllowed = 1;
    cfg.attrs = a;
    cfg.numAttrs = 1;
    cudaLaunchKernelExC(&cfg, fn, args);
}

extern "C" void kernel_launch(void* const* d_in, const int* in_sizes, int n_in,
                              void* d_out, int out_size) {
    const float* x  = (const float*)d_in[0];
    const float* w3 = (const float*)d_in[1];
    const float* b3 = (const float*)d_in[2];
    const float* w5 = (const float*)d_in[3];
    const float* b5 = (const float*)d_in[4];
    const float* w7 = (const float*)d_in[5];
    const float* b7 = (const float*)d_in[6];
    const float* w9 = (const float*)d_in[7];
    const float* b9 = (const float*)d_in[8];
    const float* nhs = (const float*)d_in[9];
    const float* nhb = (const float*)d_in[10];
    const float* nws = (const float*)d_in[11];
    const float* nwb = (const float*)d_in[12];
    const float* ns  = (const float*)d_in[13];
    const float* nb  = (const float*)d_in[14];
    const float* qw  = (const float*)d_in[15];
    const float* kw  = (const float*)d_in[16];
    const float* vw  = (const float*)d_in[17];
    float* out = (float*)d_out;

    k_means<<<BC, 256>>>(x);
    k_sa<<<dim3(4, B, 2), 512>>>(w3, b3, w5, b5, w7, b7, w9, b9, nhs, nhb, nws, nwb);

    {   // k_pool as PDL secondary of k_sa
        void* args[] = { (void*)&x };
        launch_pdl((void*)k_pool, dim3(BC / 2), dim3(256), args);
    }

    k_attn<<<dim3(HEADS, B), 256>>>(ns, nb, qw, kw, vw);

    {   // k_final as PDL secondary of k_attn
        void* args[] = { (void*)&x, (void*)&out };
        launch_pdl((void*)k_final, dim3(BC), dim3(256), args);
    }
}